// round 2
// baseline (speedup 1.0000x reference)
#include <cuda_runtime.h>
#include <math.h>

// ODE-RNN persistent kernel.
// B=1024, T=200, D=64, L=256, H=256, N_SUB=4.
// Grid: 128 CTAs x 256 threads. Each CTA owns MB=8 batch rows for the whole
// time loop. Activations live in SMEM transposed as [k][MB] so the per-output
// inner product reads x via broadcast LDS.128. Weights stream from L2
// (1.77 MB total, fully L2-resident).

#define NT 256
#define MB 8
#define T_LEN 200
#define L_DIM 256

__device__ __forceinline__ float sigm(float v) {
    return 1.0f / (1.0f + expf(-v));
}

// y[n][m] = act( bias[n] (+ tt*W[n][K] if TCOL) + sum_k W[n*LDW+k] * xs[k*MB+m] )
template<int K, int LDW, bool TANH, bool TCOL>
__device__ __forceinline__ void mmT(const float* __restrict__ W,
                                    const float* __restrict__ bias,
                                    const float* __restrict__ xs,
                                    float* __restrict__ ys,
                                    int N, float tt) {
    for (int n = threadIdx.x; n < N; n += NT) {
        const float* __restrict__ w = W + (size_t)n * LDW;
        float a0 = bias[n];
        if (TCOL) a0 += tt * w[K];
        float acc0 = 0.f, acc1 = 0.f, acc2 = 0.f, acc3 = 0.f;
        float acc4 = 0.f, acc5 = 0.f, acc6 = 0.f, acc7 = 0.f;
#pragma unroll 4
        for (int k = 0; k < K; ++k) {
            float wv = w[k];
            const float4* x4 = reinterpret_cast<const float4*>(xs + k * MB);
            float4 xa = x4[0];
            float4 xb = x4[1];
            acc0 += wv * xa.x; acc1 += wv * xa.y;
            acc2 += wv * xa.z; acc3 += wv * xa.w;
            acc4 += wv * xb.x; acc5 += wv * xb.y;
            acc6 += wv * xb.z; acc7 += wv * xb.w;
        }
        float v0 = a0 + acc0, v1 = a0 + acc1, v2 = a0 + acc2, v3 = a0 + acc3;
        float v4 = a0 + acc4, v5 = a0 + acc5, v6 = a0 + acc6, v7 = a0 + acc7;
        if (TANH) {
            v0 = tanhf(v0); v1 = tanhf(v1); v2 = tanhf(v2); v3 = tanhf(v3);
            v4 = tanhf(v4); v5 = tanhf(v5); v6 = tanhf(v6); v7 = tanhf(v7);
        }
        float4* y4 = reinterpret_cast<float4*>(ys + n * MB);
        y4[0] = make_float4(v0, v1, v2, v3);
        y4[1] = make_float4(v4, v5, v6, v7);
    }
}

__global__ void __launch_bounds__(NT, 1)
odernn_kernel(const float* __restrict__ x,
              const float* __restrict__ t,
              const float* __restrict__ mask,
              const float* __restrict__ W_ih,
              const float* __restrict__ W_hh,
              const float* __restrict__ b_ih,
              const float* __restrict__ b_hh,
              const float* __restrict__ W1,
              const float* __restrict__ b1,
              const float* __restrict__ W2,
              const float* __restrict__ b2,
              const float* __restrict__ W3,
              const float* __restrict__ b3,
              float* __restrict__ out) {
    extern __shared__ float sm[];
    // SMEM partition (all [k][MB] transposed layouts)
    float* xT = sm;            // 64*8   = 512
    float* gi = xT + 512;      // 768*8  = 6144
    float* gh = gi + 6144;     // 768*8  = 6144
    float* hT = gh + 6144;     // 256*8  = 2048
    float* yT = hT + 2048;     // 2048
    float* a1 = yT + 2048;     // 2048
    float* a2 = a1 + 2048;     // 2048
    float* fT = a2 + 2048;     // 2048
    float* ka = fT + 2048;     // 2048
    // total 25088 floats = 100352 bytes

    const int tid = threadIdx.x;
    const int m0 = blockIdx.x * MB;

    for (int idx = tid; idx < L_DIM * MB; idx += NT) hT[idx] = 0.0f;
    __syncthreads();

    for (int i = 0; i < T_LEN; ++i) {
        // load x[:, i, :] rows m0..m0+7 into xT[k][m]
        for (int idx = tid; idx < 64 * MB; idx += NT) {
            int k = idx >> 3, m = idx & 7;
            xT[idx] = x[((size_t)(m0 + m) * T_LEN + i) * 64 + k];
        }
        __syncthreads();

        // GRU gates
        mmT<64, 64, false, false>(W_ih, b_ih, xT, gi, 768, 0.f);
        mmT<256, 256, false, false>(W_hh, b_hh, hT, gh, 768, 0.f);
        __syncthreads();

        // gate pointwise + mask blend + output write
        {
            int n = tid;  // 0..255
#pragma unroll
            for (int m = 0; m < MB; ++m) {
                float ir = gi[n * MB + m];
                float iz = gi[(256 + n) * MB + m];
                float in_ = gi[(512 + n) * MB + m];
                float hr = gh[n * MB + m];
                float hz = gh[(256 + n) * MB + m];
                float hn = gh[(512 + n) * MB + m];
                float h = hT[n * MB + m];
                float r = sigm(ir + hr);
                float z = sigm(iz + hz);
                float nn = tanhf(in_ + r * hn);
                float hnew = (1.0f - z) * nn + z * h;
                float mk = mask[(size_t)(m0 + m) * T_LEN + i];
                float hobs = mk * hnew + (1.0f - mk) * h;
                hT[n * MB + m] = hobs;
                out[((size_t)(m0 + m) * T_LEN + i) * L_DIM + n] = hobs;
            }
        }
        __syncthreads();

        if (i == T_LEN - 1) break;

        // RK4 integration: h_next = integrate(h_obs, t[i], t[i+1])
        float t0 = t[i], t1 = t[i + 1];
        float dt = (t1 - t0) * 0.25f;
        float tt = t0;
        for (int sub = 0; sub < 4; ++sub) {
            // stage 1: k1 = f(tt, h)
            mmT<256, 257, true, true>(W1, b1, hT, a1, 256, tt); __syncthreads();
            mmT<256, 256, true, false>(W2, b2, a1, a2, 256, 0.f); __syncthreads();
            mmT<256, 256, false, false>(W3, b3, a2, fT, 256, 0.f); __syncthreads();
            for (int idx = tid; idx < L_DIM * MB; idx += NT) {
                float f = fT[idx];
                ka[idx] = f;
                yT[idx] = hT[idx] + (0.5f * dt) * f;
            }
            __syncthreads();
            // stage 2: k2 = f(tt+dt/2, h + dt/2*k1)
            mmT<256, 257, true, true>(W1, b1, yT, a1, 256, tt + 0.5f * dt); __syncthreads();
            mmT<256, 256, true, false>(W2, b2, a1, a2, 256, 0.f); __syncthreads();
            mmT<256, 256, false, false>(W3, b3, a2, fT, 256, 0.f); __syncthreads();
            for (int idx = tid; idx < L_DIM * MB; idx += NT) {
                float f = fT[idx];
                ka[idx] += 2.0f * f;
                yT[idx] = hT[idx] + (0.5f * dt) * f;
            }
            __syncthreads();
            // stage 3: k3 = f(tt+dt/2, h + dt/2*k2)
            mmT<256, 257, true, true>(W1, b1, yT, a1, 256, tt + 0.5f * dt); __syncthreads();
            mmT<256, 256, true, false>(W2, b2, a1, a2, 256, 0.f); __syncthreads();
            mmT<256, 256, false, false>(W3, b3, a2, fT, 256, 0.f); __syncthreads();
            for (int idx = tid; idx < L_DIM * MB; idx += NT) {
                float f = fT[idx];
                ka[idx] += 2.0f * f;
                yT[idx] = hT[idx] + dt * f;
            }
            __syncthreads();
            // stage 4: k4 = f(tt+dt, h + dt*k3); h += dt/6*(k1+2k2+2k3+k4)
            mmT<256, 257, true, true>(W1, b1, yT, a1, 256, tt + dt); __syncthreads();
            mmT<256, 256, true, false>(W2, b2, a1, a2, 256, 0.f); __syncthreads();
            mmT<256, 256, false, false>(W3, b3, a2, fT, 256, 0.f); __syncthreads();
            for (int idx = tid; idx < L_DIM * MB; idx += NT) {
                float f = fT[idx];
                hT[idx] = hT[idx] + (dt / 6.0f) * (ka[idx] + f);
            }
            __syncthreads();
            tt += dt;
        }
    }
}

extern "C" void kernel_launch(void* const* d_in, const int* in_sizes, int n_in,
                              void* d_out, int out_size) {
    const float* x    = (const float*)d_in[0];
    const float* t    = (const float*)d_in[1];
    const float* mask = (const float*)d_in[2];
    const float* W_ih = (const float*)d_in[3];
    const float* W_hh = (const float*)d_in[4];
    const float* b_ih = (const float*)d_in[5];
    const float* b_hh = (const float*)d_in[6];
    const float* W1   = (const float*)d_in[7];
    const float* b1   = (const float*)d_in[8];
    const float* W2   = (const float*)d_in[9];
    const float* b2   = (const float*)d_in[10];
    const float* W3   = (const float*)d_in[11];
    const float* b3   = (const float*)d_in[12];
    float* out = (float*)d_out;

    const int smem_bytes = 25088 * sizeof(float);  // 100352
    cudaFuncSetAttribute(odernn_kernel,
                         cudaFuncAttributeMaxDynamicSharedMemorySize, smem_bytes);

    odernn_kernel<<<128, NT, smem_bytes>>>(x, t, mask, W_ih, W_hh, b_ih, b_hh,
                                           W1, b1, W2, b2, W3, b3, out);
}

// round 3
// speedup vs baseline: 3.9206x; 3.9206x over previous
#include <cuda_runtime.h>
#include <math.h>

// ODE-RNN persistent kernel, round 3: coalesced k-packed transposed weights.
// B=1024, T=200, D=64, L=256, H=256, N_SUB=4.
// Grid: 128 CTAs x 256 threads, each CTA owns MB=8 batch rows.
// Weights are transposed+packed once per launch into __device__ buffers:
//   WT4[(k4*N + n)*4 + j] = W[n][k4*4+j]
// so thread n streams its weight column via coalesced LDG.128 (4 k per load).

#define NT 256
#define MB 8
#define T_LEN 200
#define L_DIM 256

// Packed transposed weights (k-major, 4-k packs, n contiguous)
__device__ float g_WihT[16 * 768 * 4];    // K=64
__device__ float g_WhhT[64 * 768 * 4];    // K=256
__device__ float g_W1T [64 * 256 * 4];    // K=256 (first 256 cols of 257)
__device__ float g_W1last[256];           // t-column (col 256)
__device__ float g_W2T [64 * 256 * 4];
__device__ float g_W3T [64 * 256 * 4];

__global__ void prep_kernel(const float* __restrict__ W_ih,
                            const float* __restrict__ W_hh,
                            const float* __restrict__ W1,
                            const float* __restrict__ W2,
                            const float* __restrict__ W3) {
    int idx = blockIdx.x * blockDim.x + threadIdx.x;
    int stride = gridDim.x * blockDim.x;
    // W_ih: N=768, K=64, LDW=64
    for (int t = idx; t < 16 * 768 * 4; t += stride) {
        int j = t & 3, nk = t >> 2;
        int n = nk % 768, k4 = nk / 768;
        g_WihT[t] = W_ih[n * 64 + k4 * 4 + j];
    }
    // W_hh: N=768, K=256, LDW=256
    for (int t = idx; t < 64 * 768 * 4; t += stride) {
        int j = t & 3, nk = t >> 2;
        int n = nk % 768, k4 = nk / 768;
        g_WhhT[t] = W_hh[n * 256 + k4 * 4 + j];
    }
    // W1: N=256, K=256, LDW=257 (+ last col)
    for (int t = idx; t < 64 * 256 * 4; t += stride) {
        int j = t & 3, nk = t >> 2;
        int n = nk % 256, k4 = nk / 256;
        g_W1T[t] = W1[n * 257 + k4 * 4 + j];
    }
    for (int n = idx; n < 256; n += stride) g_W1last[n] = W1[n * 257 + 256];
    // W2, W3: N=256, K=256, LDW=256
    for (int t = idx; t < 64 * 256 * 4; t += stride) {
        int j = t & 3, nk = t >> 2;
        int n = nk % 256, k4 = nk / 256;
        g_W2T[t] = W2[n * 256 + k4 * 4 + j];
        g_W3T[t] = W3[n * 256 + k4 * 4 + j];
    }
}

__device__ __forceinline__ float sigm(float v) {
    return 1.0f / (1.0f + expf(-v));
}

// ys[n][m] = act( bias[n] (+ tt*tlast[n]) + sum_k WT4[k][n] * xs[k*MB+m] )
// WT4 layout: float4 at index (k4*N + n); xs layout: [k][MB].
template<int K, bool TANH, bool TCOL>
__device__ __forceinline__ void mmT4(const float* __restrict__ WT4,
                                     const float* __restrict__ bias,
                                     const float* __restrict__ tlast, float tt,
                                     const float* __restrict__ xs,
                                     float* __restrict__ ys, int N) {
    for (int n = threadIdx.x; n < N; n += NT) {
        float a0 = bias[n];
        if (TCOL) a0 += tt * tlast[n];
        float acc0 = 0.f, acc1 = 0.f, acc2 = 0.f, acc3 = 0.f;
        float acc4 = 0.f, acc5 = 0.f, acc6 = 0.f, acc7 = 0.f;
        const float4* __restrict__ wp = reinterpret_cast<const float4*>(WT4) + n;
#pragma unroll 2
        for (int k4 = 0; k4 < K / 4; ++k4) {
            float4 w = wp[(size_t)k4 * N];
            const float4* __restrict__ x4 =
                reinterpret_cast<const float4*>(xs + (k4 * 4) * MB);
            {
                float4 xa = x4[0], xb = x4[1];
                acc0 += w.x * xa.x; acc1 += w.x * xa.y;
                acc2 += w.x * xa.z; acc3 += w.x * xa.w;
                acc4 += w.x * xb.x; acc5 += w.x * xb.y;
                acc6 += w.x * xb.z; acc7 += w.x * xb.w;
            }
            {
                float4 xa = x4[2], xb = x4[3];
                acc0 += w.y * xa.x; acc1 += w.y * xa.y;
                acc2 += w.y * xa.z; acc3 += w.y * xa.w;
                acc4 += w.y * xb.x; acc5 += w.y * xb.y;
                acc6 += w.y * xb.z; acc7 += w.y * xb.w;
            }
            {
                float4 xa = x4[4], xb = x4[5];
                acc0 += w.z * xa.x; acc1 += w.z * xa.y;
                acc2 += w.z * xa.z; acc3 += w.z * xa.w;
                acc4 += w.z * xb.x; acc5 += w.z * xb.y;
                acc6 += w.z * xb.z; acc7 += w.z * xb.w;
            }
            {
                float4 xa = x4[6], xb = x4[7];
                acc0 += w.w * xa.x; acc1 += w.w * xa.y;
                acc2 += w.w * xa.z; acc3 += w.w * xa.w;
                acc4 += w.w * xb.x; acc5 += w.w * xb.y;
                acc6 += w.w * xb.z; acc7 += w.w * xb.w;
            }
        }
        float v0 = a0 + acc0, v1 = a0 + acc1, v2 = a0 + acc2, v3 = a0 + acc3;
        float v4 = a0 + acc4, v5 = a0 + acc5, v6 = a0 + acc6, v7 = a0 + acc7;
        if (TANH) {
            v0 = tanhf(v0); v1 = tanhf(v1); v2 = tanhf(v2); v3 = tanhf(v3);
            v4 = tanhf(v4); v5 = tanhf(v5); v6 = tanhf(v6); v7 = tanhf(v7);
        }
        float4* y4 = reinterpret_cast<float4*>(ys + n * MB);
        y4[0] = make_float4(v0, v1, v2, v3);
        y4[1] = make_float4(v4, v5, v6, v7);
    }
}

__global__ void __launch_bounds__(NT, 1)
odernn_kernel(const float* __restrict__ x,
              const float* __restrict__ t,
              const float* __restrict__ mask,
              const float* __restrict__ b_ih,
              const float* __restrict__ b_hh,
              const float* __restrict__ b1,
              const float* __restrict__ b2,
              const float* __restrict__ b3,
              float* __restrict__ out) {
    extern __shared__ float sm[];
    float* xT = sm;            // 64*8   = 512
    float* gi = xT + 512;      // 768*8  = 6144
    float* gh = gi + 6144;     // 768*8  = 6144
    float* hT = gh + 6144;     // 2048
    float* yT = hT + 2048;     // 2048
    float* a1 = yT + 2048;     // 2048
    float* a2 = a1 + 2048;     // 2048
    float* fT = a2 + 2048;     // 2048
    float* ka = fT + 2048;     // 2048
    // total 25088 floats = 100352 bytes

    const int tid = threadIdx.x;
    const int m0 = blockIdx.x * MB;

    for (int idx = tid; idx < L_DIM * MB; idx += NT) hT[idx] = 0.0f;
    __syncthreads();

    for (int i = 0; i < T_LEN; ++i) {
        for (int idx = tid; idx < 64 * MB; idx += NT) {
            int k = idx >> 3, m = idx & 7;
            xT[idx] = x[((size_t)(m0 + m) * T_LEN + i) * 64 + k];
        }
        __syncthreads();

        // GRU gates
        mmT4<64, false, false>(g_WihT, b_ih, nullptr, 0.f, xT, gi, 768);
        mmT4<256, false, false>(g_WhhT, b_hh, nullptr, 0.f, hT, gh, 768);
        __syncthreads();

        // gate pointwise + mask blend + output write
        {
            int n = tid;
#pragma unroll
            for (int m = 0; m < MB; ++m) {
                float ir = gi[n * MB + m];
                float iz = gi[(256 + n) * MB + m];
                float in_ = gi[(512 + n) * MB + m];
                float hr = gh[n * MB + m];
                float hz = gh[(256 + n) * MB + m];
                float hn = gh[(512 + n) * MB + m];
                float h = hT[n * MB + m];
                float r = sigm(ir + hr);
                float z = sigm(iz + hz);
                float nn = tanhf(in_ + r * hn);
                float hnew = (1.0f - z) * nn + z * h;
                float mk = mask[(size_t)(m0 + m) * T_LEN + i];
                float hobs = mk * hnew + (1.0f - mk) * h;
                hT[n * MB + m] = hobs;
                out[((size_t)(m0 + m) * T_LEN + i) * L_DIM + n] = hobs;
            }
        }
        __syncthreads();

        if (i == T_LEN - 1) break;

        float t0 = t[i], t1 = t[i + 1];
        float dt = (t1 - t0) * 0.25f;
        float tt = t0;
        for (int sub = 0; sub < 4; ++sub) {
            // stage 1
            mmT4<256, true, true>(g_W1T, b1, g_W1last, tt, hT, a1, 256); __syncthreads();
            mmT4<256, true, false>(g_W2T, b2, nullptr, 0.f, a1, a2, 256); __syncthreads();
            mmT4<256, false, false>(g_W3T, b3, nullptr, 0.f, a2, fT, 256); __syncthreads();
            for (int idx = tid; idx < L_DIM * MB; idx += NT) {
                float f = fT[idx];
                ka[idx] = f;
                yT[idx] = hT[idx] + (0.5f * dt) * f;
            }
            __syncthreads();
            // stage 2
            mmT4<256, true, true>(g_W1T, b1, g_W1last, tt + 0.5f * dt, yT, a1, 256); __syncthreads();
            mmT4<256, true, false>(g_W2T, b2, nullptr, 0.f, a1, a2, 256); __syncthreads();
            mmT4<256, false, false>(g_W3T, b3, nullptr, 0.f, a2, fT, 256); __syncthreads();
            for (int idx = tid; idx < L_DIM * MB; idx += NT) {
                float f = fT[idx];
                ka[idx] += 2.0f * f;
                yT[idx] = hT[idx] + (0.5f * dt) * f;
            }
            __syncthreads();
            // stage 3
            mmT4<256, true, true>(g_W1T, b1, g_W1last, tt + 0.5f * dt, yT, a1, 256); __syncthreads();
            mmT4<256, true, false>(g_W2T, b2, nullptr, 0.f, a1, a2, 256); __syncthreads();
            mmT4<256, false, false>(g_W3T, b3, nullptr, 0.f, a2, fT, 256); __syncthreads();
            for (int idx = tid; idx < L_DIM * MB; idx += NT) {
                float f = fT[idx];
                ka[idx] += 2.0f * f;
                yT[idx] = hT[idx] + dt * f;
            }
            __syncthreads();
            // stage 4
            mmT4<256, true, true>(g_W1T, b1, g_W1last, tt + dt, yT, a1, 256); __syncthreads();
            mmT4<256, true, false>(g_W2T, b2, nullptr, 0.f, a1, a2, 256); __syncthreads();
            mmT4<256, false, false>(g_W3T, b3, nullptr, 0.f, a2, fT, 256); __syncthreads();
            for (int idx = tid; idx < L_DIM * MB; idx += NT) {
                float f = fT[idx];
                hT[idx] = hT[idx] + (dt / 6.0f) * (ka[idx] + f);
            }
            __syncthreads();
            tt += dt;
        }
    }
}

extern "C" void kernel_launch(void* const* d_in, const int* in_sizes, int n_in,
                              void* d_out, int out_size) {
    const float* x    = (const float*)d_in[0];
    const float* t    = (const float*)d_in[1];
    const float* mask = (const float*)d_in[2];
    const float* W_ih = (const float*)d_in[3];
    const float* W_hh = (const float*)d_in[4];
    const float* b_ih = (const float*)d_in[5];
    const float* b_hh = (const float*)d_in[6];
    const float* W1   = (const float*)d_in[7];
    const float* b1   = (const float*)d_in[8];
    const float* W2   = (const float*)d_in[9];
    const float* b2   = (const float*)d_in[10];
    const float* W3   = (const float*)d_in[11];
    const float* b3   = (const float*)d_in[12];
    float* out = (float*)d_out;

    prep_kernel<<<256, 256>>>(W_ih, W_hh, W1, W2, W3);

    const int smem_bytes = 25088 * sizeof(float);  // 100352
    cudaFuncSetAttribute(odernn_kernel,
                         cudaFuncAttributeMaxDynamicSharedMemorySize, smem_bytes);
    odernn_kernel<<<128, NT, smem_bytes>>>(x, t, mask, b_ih, b_hh,
                                           b1, b2, b3, out);
}

// round 4
// speedup vs baseline: 4.3611x; 1.1124x over previous
#include <cuda_runtime.h>
#include <math.h>

// ODE-RNN persistent kernel, round 4: 512 threads/CTA with M-split for 2x
// occupancy (latency hiding), approx-tanh in MLP.
// Grid: 128 CTAs x 512 threads. Each CTA owns MB=8 batch rows; thread half
// tid<256 handles rows 0..3, tid>=256 handles rows 4..7 of the CTA tile.

#define NT 512
#define MB 8
#define T_LEN 200
#define L_DIM 256

// Packed transposed weights (k-major, 4-k packs, n contiguous)
__device__ float g_WihT[16 * 768 * 4];    // K=64
__device__ float g_WhhT[64 * 768 * 4];    // K=256
__device__ float g_W1T [64 * 256 * 4];    // K=256 (first 256 cols of 257)
__device__ float g_W1last[256];           // t-column (col 256)
__device__ float g_W2T [64 * 256 * 4];
__device__ float g_W3T [64 * 256 * 4];

__global__ void prep_kernel(const float* __restrict__ W_ih,
                            const float* __restrict__ W_hh,
                            const float* __restrict__ W1,
                            const float* __restrict__ W2,
                            const float* __restrict__ W3) {
    int idx = blockIdx.x * blockDim.x + threadIdx.x;
    int stride = gridDim.x * blockDim.x;
    for (int t = idx; t < 16 * 768 * 4; t += stride) {
        int j = t & 3, nk = t >> 2;
        int n = nk % 768, k4 = nk / 768;
        g_WihT[t] = W_ih[n * 64 + k4 * 4 + j];
    }
    for (int t = idx; t < 64 * 768 * 4; t += stride) {
        int j = t & 3, nk = t >> 2;
        int n = nk % 768, k4 = nk / 768;
        g_WhhT[t] = W_hh[n * 256 + k4 * 4 + j];
    }
    for (int t = idx; t < 64 * 256 * 4; t += stride) {
        int j = t & 3, nk = t >> 2;
        int n = nk % 256, k4 = nk / 256;
        g_W1T[t] = W1[n * 257 + k4 * 4 + j];
    }
    for (int n = idx; n < 256; n += stride) g_W1last[n] = W1[n * 257 + 256];
    for (int t = idx; t < 64 * 256 * 4; t += stride) {
        int j = t & 3, nk = t >> 2;
        int n = nk % 256, k4 = nk / 256;
        g_W2T[t] = W2[n * 256 + k4 * 4 + j];
        g_W3T[t] = W3[n * 256 + k4 * 4 + j];
    }
}

__device__ __forceinline__ float sigm(float v) {
    return 1.0f / (1.0f + __expf(-v));
}
__device__ __forceinline__ float tanha(float v) {
    float r;
    asm("tanh.approx.f32 %0, %1;" : "=f"(r) : "f"(v));
    return r;
}

// Half-M GEMM: thread computes 4 batch rows (mh selects which half).
// ys[n][mh*4..mh*4+3] = act( bias[n] (+tt*tlast[n]) + sum_k WT4[k][n]*xs[k][m] )
template<int K, bool TANH, bool TCOL>
__device__ __forceinline__ void mmT4(const float* __restrict__ WT4,
                                     const float* __restrict__ bias,
                                     const float* __restrict__ tlast, float tt,
                                     const float* __restrict__ xs,
                                     float* __restrict__ ys, int N) {
    const int lane_n = threadIdx.x & 255;
    const int mh = threadIdx.x >> 8;  // 0 or 1
    const float4* __restrict__ x4 = reinterpret_cast<const float4*>(xs);
    for (int n = lane_n; n < N; n += 256) {
        float a0 = bias[n];
        if (TCOL) a0 += tt * tlast[n];
        float acc0 = 0.f, acc1 = 0.f, acc2 = 0.f, acc3 = 0.f;
        const float4* __restrict__ wp = reinterpret_cast<const float4*>(WT4) + n;
#pragma unroll 4
        for (int k4 = 0; k4 < K / 4; ++k4) {
            float4 w = wp[(size_t)k4 * N];
            float4 xa = x4[k4 * 8 + 0 + mh];
            float4 xb = x4[k4 * 8 + 2 + mh];
            float4 xc = x4[k4 * 8 + 4 + mh];
            float4 xd = x4[k4 * 8 + 6 + mh];
            acc0 += w.x * xa.x; acc1 += w.x * xa.y;
            acc2 += w.x * xa.z; acc3 += w.x * xa.w;
            acc0 += w.y * xb.x; acc1 += w.y * xb.y;
            acc2 += w.y * xb.z; acc3 += w.y * xb.w;
            acc0 += w.z * xc.x; acc1 += w.z * xc.y;
            acc2 += w.z * xc.z; acc3 += w.z * xc.w;
            acc0 += w.w * xd.x; acc1 += w.w * xd.y;
            acc2 += w.w * xd.z; acc3 += w.w * xd.w;
        }
        float v0 = a0 + acc0, v1 = a0 + acc1, v2 = a0 + acc2, v3 = a0 + acc3;
        if (TANH) {
            v0 = tanha(v0); v1 = tanha(v1); v2 = tanha(v2); v3 = tanha(v3);
        }
        reinterpret_cast<float4*>(ys + n * MB)[mh] = make_float4(v0, v1, v2, v3);
    }
}

__global__ void __launch_bounds__(NT, 1)
odernn_kernel(const float* __restrict__ x,
              const float* __restrict__ t,
              const float* __restrict__ mask,
              const float* __restrict__ b_ih,
              const float* __restrict__ b_hh,
              const float* __restrict__ b1,
              const float* __restrict__ b2,
              const float* __restrict__ b3,
              float* __restrict__ out) {
    extern __shared__ float sm[];
    float* xT = sm;            // 512
    float* gi = xT + 512;      // 6144
    float* gh = gi + 6144;     // 6144
    float* hT = gh + 6144;     // 2048
    float* yT = hT + 2048;     // 2048
    float* a1 = yT + 2048;     // 2048
    float* a2 = a1 + 2048;     // 2048
    float* fT = a2 + 2048;     // 2048
    float* ka = fT + 2048;     // 2048
    // total 25088 floats = 100352 bytes

    const int tid = threadIdx.x;
    const int m0 = blockIdx.x * MB;

    for (int idx = tid; idx < L_DIM * MB; idx += NT) hT[idx] = 0.0f;
    __syncthreads();

    for (int i = 0; i < T_LEN; ++i) {
        for (int idx = tid; idx < 64 * MB; idx += NT) {
            int k = idx >> 3, m = idx & 7;
            xT[idx] = x[((size_t)(m0 + m) * T_LEN + i) * 64 + k];
        }
        __syncthreads();

        // GRU gates
        mmT4<64, false, false>(g_WihT, b_ih, nullptr, 0.f, xT, gi, 768);
        mmT4<256, false, false>(g_WhhT, b_hh, nullptr, 0.f, hT, gh, 768);
        __syncthreads();

        // gate pointwise + mask blend + output write (exact tanh/sigmoid path
        // uses __expf; gates feed h directly so keep tanhf here)
        {
            int n = tid & 255;
            int mh = tid >> 8;
#pragma unroll
            for (int mm = 0; mm < 4; ++mm) {
                int m = mh * 4 + mm;
                float ir = gi[n * MB + m];
                float iz = gi[(256 + n) * MB + m];
                float in_ = gi[(512 + n) * MB + m];
                float hr = gh[n * MB + m];
                float hz = gh[(256 + n) * MB + m];
                float hn = gh[(512 + n) * MB + m];
                float h = hT[n * MB + m];
                float r = sigm(ir + hr);
                float z = sigm(iz + hz);
                float nn = tanhf(in_ + r * hn);
                float hnew = (1.0f - z) * nn + z * h;
                float mk = mask[(size_t)(m0 + m) * T_LEN + i];
                float hobs = mk * hnew + (1.0f - mk) * h;
                hT[n * MB + m] = hobs;
                out[((size_t)(m0 + m) * T_LEN + i) * L_DIM + n] = hobs;
            }
        }
        __syncthreads();

        if (i == T_LEN - 1) break;

        float t0 = t[i], t1 = t[i + 1];
        float dt = (t1 - t0) * 0.25f;
        float tt = t0;
        for (int sub = 0; sub < 4; ++sub) {
            // stage 1
            mmT4<256, true, true>(g_W1T, b1, g_W1last, tt, hT, a1, 256); __syncthreads();
            mmT4<256, true, false>(g_W2T, b2, nullptr, 0.f, a1, a2, 256); __syncthreads();
            mmT4<256, false, false>(g_W3T, b3, nullptr, 0.f, a2, fT, 256); __syncthreads();
            for (int idx = tid; idx < L_DIM * MB; idx += NT) {
                float f = fT[idx];
                ka[idx] = f;
                yT[idx] = hT[idx] + (0.5f * dt) * f;
            }
            __syncthreads();
            // stage 2
            mmT4<256, true, true>(g_W1T, b1, g_W1last, tt + 0.5f * dt, yT, a1, 256); __syncthreads();
            mmT4<256, true, false>(g_W2T, b2, nullptr, 0.f, a1, a2, 256); __syncthreads();
            mmT4<256, false, false>(g_W3T, b3, nullptr, 0.f, a2, fT, 256); __syncthreads();
            for (int idx = tid; idx < L_DIM * MB; idx += NT) {
                float f = fT[idx];
                ka[idx] += 2.0f * f;
                yT[idx] = hT[idx] + (0.5f * dt) * f;
            }
            __syncthreads();
            // stage 3
            mmT4<256, true, true>(g_W1T, b1, g_W1last, tt + 0.5f * dt, yT, a1, 256); __syncthreads();
            mmT4<256, true, false>(g_W2T, b2, nullptr, 0.f, a1, a2, 256); __syncthreads();
            mmT4<256, false, false>(g_W3T, b3, nullptr, 0.f, a2, fT, 256); __syncthreads();
            for (int idx = tid; idx < L_DIM * MB; idx += NT) {
                float f = fT[idx];
                ka[idx] += 2.0f * f;
                yT[idx] = hT[idx] + dt * f;
            }
            __syncthreads();
            // stage 4
            mmT4<256, true, true>(g_W1T, b1, g_W1last, tt + dt, yT, a1, 256); __syncthreads();
            mmT4<256, true, false>(g_W2T, b2, nullptr, 0.f, a1, a2, 256); __syncthreads();
            mmT4<256, false, false>(g_W3T, b3, nullptr, 0.f, a2, fT, 256); __syncthreads();
            for (int idx = tid; idx < L_DIM * MB; idx += NT) {
                float f = fT[idx];
                hT[idx] = hT[idx] + (dt / 6.0f) * (ka[idx] + f);
            }
            __syncthreads();
            tt += dt;
        }
    }
}

extern "C" void kernel_launch(void* const* d_in, const int* in_sizes, int n_in,
                              void* d_out, int out_size) {
    const float* x    = (const float*)d_in[0];
    const float* t    = (const float*)d_in[1];
    const float* mask = (const float*)d_in[2];
    const float* W_ih = (const float*)d_in[3];
    const float* W_hh = (const float*)d_in[4];
    const float* b_ih = (const float*)d_in[5];
    const float* b_hh = (const float*)d_in[6];
    const float* W1   = (const float*)d_in[7];
    const float* b1   = (const float*)d_in[8];
    const float* W2   = (const float*)d_in[9];
    const float* b2   = (const float*)d_in[10];
    const float* W3   = (const float*)d_in[11];
    const float* b3   = (const float*)d_in[12];
    float* out = (float*)d_out;

    prep_kernel<<<256, 256>>>(W_ih, W_hh, W1, W2, W3);

    const int smem_bytes = 25088 * sizeof(float);  // 100352
    cudaFuncSetAttribute(odernn_kernel,
                         cudaFuncAttributeMaxDynamicSharedMemorySize, smem_bytes);
    odernn_kernel<<<128, NT, smem_bytes>>>(x, t, mask, b_ih, b_hh,
                                           b1, b2, b3, out);
}

// round 5
// speedup vs baseline: 7.1567x; 1.6410x over previous
#include <cuda_runtime.h>
#include <math.h>

// ODE-RNN persistent kernel, round 5:
//  - MLP GEMMs (93% of MACs) use packed dual-fp32 fma.rn.f32x2 with 2n x 8m
//    register blocking and 4-way k-split (all 512 threads active), partials
//    reduced in SMEM with fused bias/tanh/RK4-stage epilogues.
//  - Quad-packed weights WQ[k2*128+n2] = {W[n][k],W[n+1][k],W[n][k+1],W[n+1][k+1]}
//    give 1 coalesced LDG.128 + 4 broadcast LDS.128 per 32 MACs.
// Grid: 128 CTAs x 512 threads, MB=8 rows per CTA.

#define NT 512
#define MB 8
#define T_LEN 200
#define L_DIM 256

// GRU packed transposed weights (k-major, 4-k packs, n contiguous)
__device__ float g_WihT[16 * 768 * 4];    // K=64
__device__ float g_WhhT[64 * 768 * 4];    // K=256
// MLP quad-packed weights: [k2][n2] float4, 128x128 each
__device__ float4 g_W1Q[128 * 128];
__device__ float4 g_W2Q[128 * 128];
__device__ float4 g_W3Q[128 * 128];
__device__ float  g_W1last[256];          // t-column of W1 (col 256)

__global__ void prep_kernel(const float* __restrict__ W_ih,
                            const float* __restrict__ W_hh,
                            const float* __restrict__ W1,
                            const float* __restrict__ W2,
                            const float* __restrict__ W3) {
    int idx = blockIdx.x * blockDim.x + threadIdx.x;
    int stride = gridDim.x * blockDim.x;
    for (int t = idx; t < 16 * 768 * 4; t += stride) {
        int j = t & 3, nk = t >> 2;
        int n = nk % 768, k4 = nk / 768;
        g_WihT[t] = W_ih[n * 64 + k4 * 4 + j];
    }
    for (int t = idx; t < 64 * 768 * 4; t += stride) {
        int j = t & 3, nk = t >> 2;
        int n = nk % 768, k4 = nk / 768;
        g_WhhT[t] = W_hh[n * 256 + k4 * 4 + j];
    }
    // MLP quads
    for (int t = idx; t < 128 * 128; t += stride) {
        int n2 = t & 127, k2 = t >> 7;
        int n = n2 * 2, k = k2 * 2;
        g_W1Q[t] = make_float4(W1[n * 257 + k],     W1[(n + 1) * 257 + k],
                               W1[n * 257 + k + 1], W1[(n + 1) * 257 + k + 1]);
        g_W2Q[t] = make_float4(W2[n * 256 + k],     W2[(n + 1) * 256 + k],
                               W2[n * 256 + k + 1], W2[(n + 1) * 256 + k + 1]);
        g_W3Q[t] = make_float4(W3[n * 256 + k],     W3[(n + 1) * 256 + k],
                               W3[n * 256 + k + 1], W3[(n + 1) * 256 + k + 1]);
    }
    for (int n = idx; n < 256; n += stride) g_W1last[n] = W1[n * 257 + 256];
}

__device__ __forceinline__ float sigm(float v) {
    return 1.0f / (1.0f + __expf(-v));
}
__device__ __forceinline__ float tanha(float v) {
    float r;
    asm("tanh.approx.f32 %0, %1;" : "=f"(r) : "f"(v));
    return r;
}
__device__ __forceinline__ unsigned long long pk2(float a, float b) {
    unsigned long long r;
    asm("mov.b64 %0, {%1, %2};" : "=l"(r) : "f"(a), "f"(b));
    return r;
}
__device__ __forceinline__ unsigned long long ffma2(unsigned long long a,
                                                    unsigned long long b,
                                                    unsigned long long c) {
    unsigned long long d;
    asm("fma.rn.f32x2 %0, %1, %2, %3;" : "=l"(d) : "l"(a), "l"(b), "l"(c));
    return d;
}

// ---- MLP GEMM accumulate: part[ks][n][m] = sum over k-chunk of W*x ----
// WQ: quad-packed 128x128, xs: [k][MB] smem, part: 4*2048 floats smem.
__device__ __forceinline__ void mlp_acc(const float4* __restrict__ WQ,
                                        const float* __restrict__ xs,
                                        float* __restrict__ part) {
    const int n2 = threadIdx.x & 127;
    const int ks = threadIdx.x >> 7;
    unsigned long long a0[4], a1[4];
#pragma unroll
    for (int p = 0; p < 4; ++p) { a0[p] = 0ULL; a1[p] = 0ULL; }
    const float4* __restrict__ x4 = reinterpret_cast<const float4*>(xs);
    const int k2beg = ks * 32;
#pragma unroll 4
    for (int k2 = k2beg; k2 < k2beg + 32; ++k2) {
        float4 w = WQ[k2 * 128 + n2];
        unsigned long long w00 = pk2(w.x, w.x), w01 = pk2(w.y, w.y);
        unsigned long long w10 = pk2(w.z, w.z), w11 = pk2(w.w, w.w);
        float4 xa = x4[k2 * 4 + 0], xb = x4[k2 * 4 + 1];   // k = 2*k2
        float4 xc = x4[k2 * 4 + 2], xd = x4[k2 * 4 + 3];   // k+1
        unsigned long long xk0 = pk2(xa.x, xa.y), xk1 = pk2(xa.z, xa.w);
        unsigned long long xk2p = pk2(xb.x, xb.y), xk3 = pk2(xb.z, xb.w);
        unsigned long long xl0 = pk2(xc.x, xc.y), xl1 = pk2(xc.z, xc.w);
        unsigned long long xl2 = pk2(xd.x, xd.y), xl3 = pk2(xd.z, xd.w);
        a0[0] = ffma2(w00, xk0, a0[0]); a1[0] = ffma2(w01, xk0, a1[0]);
        a0[1] = ffma2(w00, xk1, a0[1]); a1[1] = ffma2(w01, xk1, a1[1]);
        a0[2] = ffma2(w00, xk2p, a0[2]); a1[2] = ffma2(w01, xk2p, a1[2]);
        a0[3] = ffma2(w00, xk3, a0[3]); a1[3] = ffma2(w01, xk3, a1[3]);
        a0[0] = ffma2(w10, xl0, a0[0]); a1[0] = ffma2(w11, xl0, a1[0]);
        a0[1] = ffma2(w10, xl1, a0[1]); a1[1] = ffma2(w11, xl1, a1[1]);
        a0[2] = ffma2(w10, xl2, a0[2]); a1[2] = ffma2(w11, xl2, a1[2]);
        a0[3] = ffma2(w10, xl3, a0[3]); a1[3] = ffma2(w11, xl3, a1[3]);
    }
    unsigned long long* ps = reinterpret_cast<unsigned long long*>(part);
    const int b0 = ks * 1024 + n2 * 8;  // ull index: n=2*n2 row
#pragma unroll
    for (int p = 0; p < 4; ++p) {
        ps[b0 + p] = a0[p];
        ps[b0 + 4 + p] = a1[p];
    }
}

// ---- reduce partials + bias (+tt*tlast) + tanh -> ys ----
__device__ __forceinline__ void mlp_reduce_tanh(const float* __restrict__ part,
                                                const float* __restrict__ bias,
                                                const float* __restrict__ tlast,
                                                float tt, bool tcol,
                                                float* __restrict__ ys) {
    const int tid = threadIdx.x;
    const float4* __restrict__ p4 = reinterpret_cast<const float4*>(part);
    float4 s0 = p4[tid], s1 = p4[512 + tid], s2 = p4[1024 + tid], s3 = p4[1536 + tid];
    const int n = tid >> 1;
    float b = bias[n];
    if (tcol) b += tt * tlast[n];
    float4 r;
    r.x = tanha(b + s0.x + s1.x + s2.x + s3.x);
    r.y = tanha(b + s0.y + s1.y + s2.y + s3.y);
    r.z = tanha(b + s0.z + s1.z + s2.z + s3.z);
    r.w = tanha(b + s0.w + s1.w + s2.w + s3.w);
    reinterpret_cast<float4*>(ys)[tid] = r;
}

// ---- reduce W3 partials + b3, fused RK4 stage update ----
template<int STAGE>
__device__ __forceinline__ void mlp_reduce_stage(const float* __restrict__ part,
                                                 const float* __restrict__ b3,
                                                 float* __restrict__ hT,
                                                 float* __restrict__ yT,
                                                 float* __restrict__ ka,
                                                 float dt) {
    const int tid = threadIdx.x;
    const float4* __restrict__ p4 = reinterpret_cast<const float4*>(part);
    float4 s0 = p4[tid], s1 = p4[512 + tid], s2 = p4[1024 + tid], s3 = p4[1536 + tid];
    float b = b3[tid >> 1];
    float4 f;
    f.x = b + s0.x + s1.x + s2.x + s3.x;
    f.y = b + s0.y + s1.y + s2.y + s3.y;
    f.z = b + s0.z + s1.z + s2.z + s3.z;
    f.w = b + s0.w + s1.w + s2.w + s3.w;
    float4* h4 = reinterpret_cast<float4*>(hT);
    float4* y4 = reinterpret_cast<float4*>(yT);
    float4* k4 = reinterpret_cast<float4*>(ka);
    float4 h = h4[tid];
    if (STAGE == 1) {
        k4[tid] = f;
        float c = 0.5f * dt;
        y4[tid] = make_float4(h.x + c * f.x, h.y + c * f.y, h.z + c * f.z, h.w + c * f.w);
    } else if (STAGE == 2) {
        float4 kk = k4[tid];
        k4[tid] = make_float4(kk.x + 2.f * f.x, kk.y + 2.f * f.y,
                              kk.z + 2.f * f.z, kk.w + 2.f * f.w);
        float c = 0.5f * dt;
        y4[tid] = make_float4(h.x + c * f.x, h.y + c * f.y, h.z + c * f.z, h.w + c * f.w);
    } else if (STAGE == 3) {
        float4 kk = k4[tid];
        k4[tid] = make_float4(kk.x + 2.f * f.x, kk.y + 2.f * f.y,
                              kk.z + 2.f * f.z, kk.w + 2.f * f.w);
        y4[tid] = make_float4(h.x + dt * f.x, h.y + dt * f.y,
                              h.z + dt * f.z, h.w + dt * f.w);
    } else {
        float4 kk = k4[tid];
        float c = dt * (1.0f / 6.0f);
        h4[tid] = make_float4(h.x + c * (kk.x + f.x), h.y + c * (kk.y + f.y),
                              h.z + c * (kk.z + f.z), h.w + c * (kk.w + f.w));
    }
}

// ---- GRU GEMM (round-4 style, 7% of MACs) ----
template<int K>
__device__ __forceinline__ void mmT4(const float* __restrict__ WT4,
                                     const float* __restrict__ bias,
                                     const float* __restrict__ xs,
                                     float* __restrict__ ys, int N) {
    const int lane_n = threadIdx.x & 255;
    const int mh = threadIdx.x >> 8;
    const float4* __restrict__ x4 = reinterpret_cast<const float4*>(xs);
    for (int n = lane_n; n < N; n += 256) {
        float a0 = bias[n];
        float acc0 = 0.f, acc1 = 0.f, acc2 = 0.f, acc3 = 0.f;
        const float4* __restrict__ wp = reinterpret_cast<const float4*>(WT4) + n;
#pragma unroll 4
        for (int k4 = 0; k4 < K / 4; ++k4) {
            float4 w = wp[(size_t)k4 * N];
            float4 xa = x4[k4 * 8 + 0 + mh];
            float4 xb = x4[k4 * 8 + 2 + mh];
            float4 xc = x4[k4 * 8 + 4 + mh];
            float4 xd = x4[k4 * 8 + 6 + mh];
            acc0 += w.x * xa.x; acc1 += w.x * xa.y;
            acc2 += w.x * xa.z; acc3 += w.x * xa.w;
            acc0 += w.y * xb.x; acc1 += w.y * xb.y;
            acc2 += w.y * xb.z; acc3 += w.y * xb.w;
            acc0 += w.z * xc.x; acc1 += w.z * xc.y;
            acc2 += w.z * xc.z; acc3 += w.z * xc.w;
            acc0 += w.w * xd.x; acc1 += w.w * xd.y;
            acc2 += w.w * xd.z; acc3 += w.w * xd.w;
        }
        reinterpret_cast<float4*>(ys + n * MB)[mh] =
            make_float4(a0 + acc0, a0 + acc1, a0 + acc2, a0 + acc3);
    }
}

__global__ void __launch_bounds__(NT, 1)
odernn_kernel(const float* __restrict__ x,
              const float* __restrict__ t,
              const float* __restrict__ mask,
              const float* __restrict__ b_ih,
              const float* __restrict__ b_hh,
              const float* __restrict__ b1,
              const float* __restrict__ b2,
              const float* __restrict__ b3,
              float* __restrict__ out) {
    extern __shared__ float sm[];
    float* xT = sm;            // 512
    float* gi = xT + 512;      // 6144 (also MLP partial buffer, 8192 w/ gh)
    float* gh = gi + 6144;     // 6144
    float* hT = gh + 6144;     // 2048
    float* yT = hT + 2048;     // 2048
    float* a1 = yT + 2048;     // 2048
    float* a2 = a1 + 2048;     // 2048
    float* ka = a2 + 2048;     // 2048
    float* part = gi;          // 4*2048 = 8192 floats (fits in gi+gh)
    // total 23040 floats = 92160 bytes

    const int tid = threadIdx.x;
    const int m0 = blockIdx.x * MB;

    for (int idx = tid; idx < L_DIM * MB; idx += NT) hT[idx] = 0.0f;
    __syncthreads();

    for (int i = 0; i < T_LEN; ++i) {
        for (int idx = tid; idx < 64 * MB; idx += NT) {
            int k = idx >> 3, m = idx & 7;
            xT[idx] = x[((size_t)(m0 + m) * T_LEN + i) * 64 + k];
        }
        __syncthreads();

        // GRU gates
        mmT4<64>(g_WihT, b_ih, xT, gi, 768);
        mmT4<256>(g_WhhT, b_hh, hT, gh, 768);
        __syncthreads();

        // gate pointwise + mask blend + output write
        {
            int n = tid & 255;
            int mh = tid >> 8;
#pragma unroll
            for (int mm = 0; mm < 4; ++mm) {
                int m = mh * 4 + mm;
                float ir = gi[n * MB + m];
                float iz = gi[(256 + n) * MB + m];
                float in_ = gi[(512 + n) * MB + m];
                float hr = gh[n * MB + m];
                float hz = gh[(256 + n) * MB + m];
                float hn = gh[(512 + n) * MB + m];
                float h = hT[n * MB + m];
                float r = sigm(ir + hr);
                float z = sigm(iz + hz);
                float nn = tanhf(in_ + r * hn);
                float hnew = (1.0f - z) * nn + z * h;
                float mk = mask[(size_t)(m0 + m) * T_LEN + i];
                float hobs = mk * hnew + (1.0f - mk) * h;
                hT[n * MB + m] = hobs;
                out[((size_t)(m0 + m) * T_LEN + i) * L_DIM + n] = hobs;
            }
        }
        __syncthreads();

        if (i == T_LEN - 1) break;

        float t0 = t[i], t1 = t[i + 1];
        float dt = (t1 - t0) * 0.25f;
        float tt = t0;
        for (int sub = 0; sub < 4; ++sub) {
            // stage 1: f(tt, hT)
            mlp_acc(g_W1Q, hT, part); __syncthreads();
            mlp_reduce_tanh(part, b1, g_W1last, tt, true, a1); __syncthreads();
            mlp_acc(g_W2Q, a1, part); __syncthreads();
            mlp_reduce_tanh(part, b2, nullptr, 0.f, false, a2); __syncthreads();
            mlp_acc(g_W3Q, a2, part); __syncthreads();
            mlp_reduce_stage<1>(part, b3, hT, yT, ka, dt); __syncthreads();
            // stage 2: f(tt+dt/2, yT)
            mlp_acc(g_W1Q, yT, part); __syncthreads();
            mlp_reduce_tanh(part, b1, g_W1last, tt + 0.5f * dt, true, a1); __syncthreads();
            mlp_acc(g_W2Q, a1, part); __syncthreads();
            mlp_reduce_tanh(part, b2, nullptr, 0.f, false, a2); __syncthreads();
            mlp_acc(g_W3Q, a2, part); __syncthreads();
            mlp_reduce_stage<2>(part, b3, hT, yT, ka, dt); __syncthreads();
            // stage 3: f(tt+dt/2, yT)
            mlp_acc(g_W1Q, yT, part); __syncthreads();
            mlp_reduce_tanh(part, b1, g_W1last, tt + 0.5f * dt, true, a1); __syncthreads();
            mlp_acc(g_W2Q, a1, part); __syncthreads();
            mlp_reduce_tanh(part, b2, nullptr, 0.f, false, a2); __syncthreads();
            mlp_acc(g_W3Q, a2, part); __syncthreads();
            mlp_reduce_stage<3>(part, b3, hT, yT, ka, dt); __syncthreads();
            // stage 4: f(tt+dt, yT)
            mlp_acc(g_W1Q, yT, part); __syncthreads();
            mlp_reduce_tanh(part, b1, g_W1last, tt + dt, true, a1); __syncthreads();
            mlp_acc(g_W2Q, a1, part); __syncthreads();
            mlp_reduce_tanh(part, b2, nullptr, 0.f, false, a2); __syncthreads();
            mlp_acc(g_W3Q, a2, part); __syncthreads();
            mlp_reduce_stage<4>(part, b3, hT, yT, ka, dt); __syncthreads();
            tt += dt;
        }
    }
}

extern "C" void kernel_launch(void* const* d_in, const int* in_sizes, int n_in,
                              void* d_out, int out_size) {
    const float* x    = (const float*)d_in[0];
    const float* t    = (const float*)d_in[1];
    const float* mask = (const float*)d_in[2];
    const float* W_ih = (const float*)d_in[3];
    const float* W_hh = (const float*)d_in[4];
    const float* b_ih = (const float*)d_in[5];
    const float* b_hh = (const float*)d_in[6];
    const float* W1   = (const float*)d_in[7];
    const float* b1   = (const float*)d_in[8];
    const float* W2   = (const float*)d_in[9];
    const float* b2   = (const float*)d_in[10];
    const float* W3   = (const float*)d_in[11];
    const float* b3   = (const float*)d_in[12];
    float* out = (float*)d_out;

    prep_kernel<<<256, 256>>>(W_ih, W_hh, W1, W2, W3);

    const int smem_bytes = 23040 * sizeof(float);  // 92160
    cudaFuncSetAttribute(odernn_kernel,
                         cudaFuncAttributeMaxDynamicSharedMemorySize, smem_bytes);
    odernn_kernel<<<128, NT, smem_bytes>>>(x, t, mask, b_ih, b_hh,
                                           b1, b2, b3, out);
}

// round 6
// speedup vs baseline: 8.6222x; 1.2048x over previous
#include <cuda_runtime.h>
#include <math.h>

// ODE-RNN persistent kernel, round 6:
//  - MLP GEMMs via tf32 mma.sync.m16n8k8 (weights pre-packed to A-fragment
//    layout; 1 coalesced LDG.128 per mma). Each of 16 warps owns one 16-row
//    n-tile for the FULL K => no partial reduction, accumulators in regs.
//  - MB=16 rows/CTA, 64 CTAs: halves L2 weight traffic per step vs MB=8.
//  - GRU stays exact fp32 FFMA2 (recurrence-critical path).
//  - Activation buffers padded to row stride 24 floats => conflict-free
//    B-fragment LDS.32 (bank = 24*tig + gid covers 0..31).

#define NT 512
#define MBR 16
#define NCTA 64
#define T_LEN 200
#define XS 24   // activation row stride in floats

typedef unsigned long long ull;

// GRU packed transposed weights (k-major, 4-k packs, n contiguous)
__device__ float g_WihT[16 * 768 * 4];
__device__ float g_WhhT[64 * 768 * 4];
// MLP tf32 fragment-packed weights: [nt(16)][kt(32)][lane(32)][a0..a3]
__device__ unsigned g_W1F[16 * 32 * 32 * 4];
__device__ unsigned g_W2F[16 * 32 * 32 * 4];
__device__ unsigned g_W3F[16 * 32 * 32 * 4];
__device__ float g_W1last[256];

__device__ __forceinline__ unsigned tf32r(float f) {
    unsigned u;
    asm("cvt.rna.tf32.f32 %0, %1;" : "=r"(u) : "f"(f));
    return u;
}

__global__ void prep_kernel(const float* __restrict__ W_ih,
                            const float* __restrict__ W_hh,
                            const float* __restrict__ W1,
                            const float* __restrict__ W2,
                            const float* __restrict__ W3) {
    int idx = blockIdx.x * blockDim.x + threadIdx.x;
    int stride = gridDim.x * blockDim.x;
    for (int t = idx; t < 16 * 768 * 4; t += stride) {
        int j = t & 3, nk = t >> 2;
        int n = nk % 768, k4 = nk / 768;
        g_WihT[t] = W_ih[n * 64 + k4 * 4 + j];
    }
    for (int t = idx; t < 64 * 768 * 4; t += stride) {
        int j = t & 3, nk = t >> 2;
        int n = nk % 768, k4 = nk / 768;
        g_WhhT[t] = W_hh[n * 256 + k4 * 4 + j];
    }
    // MLP fragment packs: a0=(r0,c0) a1=(r1,c0) a2=(r0,c1) a3=(r1,c1)
    for (int tI = idx; tI < 16 * 32 * 32; tI += stride) {
        int l = tI & 31, kt = (tI >> 5) & 31, nt = tI >> 10;
        int gid = l >> 2, tig = l & 3;
        int r0 = nt * 16 + gid, r1 = r0 + 8;
        int c0 = kt * 8 + tig, c1 = c0 + 4;
        g_W1F[tI * 4 + 0] = tf32r(W1[r0 * 257 + c0]);
        g_W1F[tI * 4 + 1] = tf32r(W1[r1 * 257 + c0]);
        g_W1F[tI * 4 + 2] = tf32r(W1[r0 * 257 + c1]);
        g_W1F[tI * 4 + 3] = tf32r(W1[r1 * 257 + c1]);
        g_W2F[tI * 4 + 0] = tf32r(W2[r0 * 256 + c0]);
        g_W2F[tI * 4 + 1] = tf32r(W2[r1 * 256 + c0]);
        g_W2F[tI * 4 + 2] = tf32r(W2[r0 * 256 + c1]);
        g_W2F[tI * 4 + 3] = tf32r(W2[r1 * 256 + c1]);
        g_W3F[tI * 4 + 0] = tf32r(W3[r0 * 256 + c0]);
        g_W3F[tI * 4 + 1] = tf32r(W3[r1 * 256 + c0]);
        g_W3F[tI * 4 + 2] = tf32r(W3[r0 * 256 + c1]);
        g_W3F[tI * 4 + 3] = tf32r(W3[r1 * 256 + c1]);
    }
    for (int n = idx; n < 256; n += stride) g_W1last[n] = W1[n * 257 + 256];
}

__device__ __forceinline__ float sigm(float v) {
    return 1.0f / (1.0f + __expf(-v));
}
__device__ __forceinline__ float tanha(float v) {
    float r;
    asm("tanh.approx.f32 %0, %1;" : "=f"(r) : "f"(v));
    return r;
}
__device__ __forceinline__ ull pk2(float a, float b) {
    ull r;
    asm("mov.b64 %0, {%1, %2};" : "=l"(r) : "f"(a), "f"(b));
    return r;
}
__device__ __forceinline__ ull ffma2(ull a, ull b, ull c) {
    ull d;
    asm("fma.rn.f32x2 %0, %1, %2, %3;" : "=l"(d) : "l"(a), "l"(b), "l"(c));
    return d;
}

#define MMA_TF32(c0, c1, c2, c3, A0, A1, A2, A3, B0, B1)                      \
    asm volatile(                                                             \
        "mma.sync.aligned.m16n8k8.row.col.f32.tf32.tf32.f32 "                 \
        "{%0,%1,%2,%3}, {%4,%5,%6,%7}, {%8,%9}, {%0,%1,%2,%3};"               \
        : "+f"(c0), "+f"(c1), "+f"(c2), "+f"(c3)                              \
        : "r"(A0), "r"(A1), "r"(A2), "r"(A3), "r"(B0), "r"(B1))

// One MLP GEMM: D[256][16] = W @ xs, warp w owns n-rows [16w,16w+16), full K.
// EPI: 0 = bias(+tt*w1l)+tanh -> dst ; 1..4 = RK4 stage update fused.
template<int EPI>
__device__ __forceinline__ void gemm16(const unsigned* __restrict__ WF,
                                       const float* __restrict__ xs,
                                       float* __restrict__ dst,
                                       const float* __restrict__ bias,
                                       const float* __restrict__ w1l,
                                       float tt, bool tcol,
                                       float* __restrict__ hT,
                                       float* __restrict__ yT,
                                       float* __restrict__ ka,
                                       const float* __restrict__ b3s,
                                       float dt) {
    const int warp = threadIdx.x >> 5;
    const int lane = threadIdx.x & 31;
    const int gid = lane >> 2, tig = lane & 3;
    float c00 = 0.f, c01 = 0.f, c02 = 0.f, c03 = 0.f;
    float c10 = 0.f, c11 = 0.f, c12 = 0.f, c13 = 0.f;
    const float4* __restrict__ wp =
        reinterpret_cast<const float4*>(WF) + (warp * 32 * 32 + lane);
    const float* __restrict__ bp = xs + tig * XS + gid;
#pragma unroll 4
    for (int kt = 0; kt < 32; ++kt) {
        float4 af = wp[kt * 32];
        unsigned A0 = __float_as_uint(af.x), A1 = __float_as_uint(af.y);
        unsigned A2 = __float_as_uint(af.z), A3 = __float_as_uint(af.w);
        const float* __restrict__ b = bp + kt * 8 * XS;
        unsigned B0 = tf32r(b[0]);
        unsigned B1 = tf32r(b[4 * XS]);
        unsigned B2 = tf32r(b[8]);
        unsigned B3 = tf32r(b[4 * XS + 8]);
        MMA_TF32(c00, c01, c02, c03, A0, A1, A2, A3, B0, B1);
        MMA_TF32(c10, c11, c12, c13, A0, A1, A2, A3, B2, B3);
    }
    const int r0 = warp * 16 + gid, r1 = r0 + 8;
    const int mc = 2 * tig;
    if (EPI == 0) {
        float bb0 = bias[r0], bb1 = bias[r1];
        if (tcol) { bb0 += tt * w1l[r0]; bb1 += tt * w1l[r1]; }
        *reinterpret_cast<float2*>(&dst[r0 * XS + mc]) =
            make_float2(tanha(bb0 + c00), tanha(bb0 + c01));
        *reinterpret_cast<float2*>(&dst[r1 * XS + mc]) =
            make_float2(tanha(bb1 + c02), tanha(bb1 + c03));
        *reinterpret_cast<float2*>(&dst[r0 * XS + 8 + mc]) =
            make_float2(tanha(bb0 + c10), tanha(bb0 + c11));
        *reinterpret_cast<float2*>(&dst[r1 * XS + 8 + mc]) =
            make_float2(tanha(bb1 + c12), tanha(bb1 + c13));
    } else {
        float b0 = b3s[r0], b1 = b3s[r1];
#pragma unroll
        for (int q = 0; q < 4; ++q) {
            int r = (q & 1) ? r1 : r0;
            int m = ((q >> 1) ? 8 : 0) + mc;
            float f0 = ((q & 1) ? b1 : b0) +
                       (q == 0 ? c00 : q == 1 ? c02 : q == 2 ? c10 : c12);
            float f1 = ((q & 1) ? b1 : b0) +
                       (q == 0 ? c01 : q == 1 ? c03 : q == 2 ? c11 : c13);
            float2 h = *reinterpret_cast<float2*>(&hT[r * XS + m]);
            if (EPI == 1) {
                *reinterpret_cast<float2*>(&ka[r * XS + m]) = make_float2(f0, f1);
                float c = 0.5f * dt;
                *reinterpret_cast<float2*>(&yT[r * XS + m]) =
                    make_float2(h.x + c * f0, h.y + c * f1);
            } else if (EPI == 2 || EPI == 3) {
                float2 kk = *reinterpret_cast<float2*>(&ka[r * XS + m]);
                *reinterpret_cast<float2*>(&ka[r * XS + m]) =
                    make_float2(kk.x + 2.f * f0, kk.y + 2.f * f1);
                float c = (EPI == 2) ? 0.5f * dt : dt;
                *reinterpret_cast<float2*>(&yT[r * XS + m]) =
                    make_float2(h.x + c * f0, h.y + c * f1);
            } else {
                float2 kk = *reinterpret_cast<float2*>(&ka[r * XS + m]);
                float c = dt * (1.0f / 6.0f);
                *reinterpret_cast<float2*>(&hT[r * XS + m]) =
                    make_float2(h.x + c * (kk.x + f0), h.y + c * (kk.y + f1));
            }
        }
    }
}

// GRU GEMM, fp32 FFMA2, 8 m per thread (mh = m-half), xs row stride XS.
template<int K>
__device__ __forceinline__ void gru_mm(const float* __restrict__ WT4,
                                       const float* __restrict__ bias,
                                       const float* __restrict__ xs,
                                       float* __restrict__ ys, int N) {
    const int n0 = threadIdx.x & 255;
    const int mh = threadIdx.x >> 8;
    const float* __restrict__ xb = xs + mh * 8;
    for (int n = n0; n < N; n += 256) {
        float a0 = bias[n];
        ull acc0 = 0ULL, acc1 = 0ULL, acc2 = 0ULL, acc3 = 0ULL;
        const float4* __restrict__ wp = reinterpret_cast<const float4*>(WT4) + n;
#pragma unroll 2
        for (int k4 = 0; k4 < K / 4; ++k4) {
            float4 w = wp[(size_t)k4 * N];
            const float* __restrict__ xr = xb + (k4 * 4) * XS;
#pragma unroll
            for (int kk = 0; kk < 4; ++kk) {
                float wv = (kk == 0 ? w.x : kk == 1 ? w.y : kk == 2 ? w.z : w.w);
                ull wd = pk2(wv, wv);
                float4 xa = *reinterpret_cast<const float4*>(xr + kk * XS);
                float4 xbv = *reinterpret_cast<const float4*>(xr + kk * XS + 4);
                acc0 = ffma2(wd, pk2(xa.x, xa.y), acc0);
                acc1 = ffma2(wd, pk2(xa.z, xa.w), acc1);
                acc2 = ffma2(wd, pk2(xbv.x, xbv.y), acc2);
                acc3 = ffma2(wd, pk2(xbv.z, xbv.w), acc3);
            }
        }
        float2 p0 = *reinterpret_cast<float2*>(&acc0);
        float2 p1 = *reinterpret_cast<float2*>(&acc1);
        float2 p2 = *reinterpret_cast<float2*>(&acc2);
        float2 p3 = *reinterpret_cast<float2*>(&acc3);
        float* yp = ys + n * 16 + mh * 8;
        *reinterpret_cast<float4*>(yp) =
            make_float4(a0 + p0.x, a0 + p0.y, a0 + p1.x, a0 + p1.y);
        *reinterpret_cast<float4*>(yp + 4) =
            make_float4(a0 + p2.x, a0 + p2.y, a0 + p3.x, a0 + p3.y);
    }
}

__global__ void __launch_bounds__(NT, 1)
odernn_kernel(const float* __restrict__ x,
              const float* __restrict__ t,
              const float* __restrict__ mask,
              const float* __restrict__ b_ih,
              const float* __restrict__ b_hh,
              const float* __restrict__ b1,
              const float* __restrict__ b2,
              const float* __restrict__ b3,
              float* __restrict__ out) {
    extern __shared__ float sm[];
    float* xT = sm;              // 64*24  = 1536
    float* hT = sm + 1536;       // 256*24 = 6144
    float* U  = sm + 7680;       // union region 24576 floats
    float* gi = U;               // 768*16 = 12288 (GRU phase)
    float* gh = U + 12288;       // 12288
    float* yT = U;               // 6144 (RK4 phase)
    float* a1 = U + 6144;        // 6144
    float* a2 = U + 12288;       // 6144
    float* ka = U + 18432;       // 6144
    float* bihs = sm + 32256;    // 768
    float* bhhs = bihs + 768;    // 768
    float* b1s  = bhhs + 768;    // 256
    float* b2s  = b1s + 256;     // 256
    float* b3s  = b2s + 256;     // 256
    float* w1ls = b3s + 256;     // 256
    // total 34816 floats = 139264 bytes

    const int tid = threadIdx.x;
    const int m0 = blockIdx.x * MBR;

    for (int idx = tid; idx < 768; idx += NT) { bihs[idx] = b_ih[idx]; bhhs[idx] = b_hh[idx]; }
    for (int idx = tid; idx < 256; idx += NT) {
        b1s[idx] = b1[idx]; b2s[idx] = b2[idx]; b3s[idx] = b3[idx];
        w1ls[idx] = g_W1last[idx];
    }
    for (int idx = tid; idx < 256 * XS; idx += NT) hT[idx] = 0.0f;
    __syncthreads();

    for (int i = 0; i < T_LEN; ++i) {
        for (int idx = tid; idx < 64 * MBR; idx += NT) {
            int k = idx & 63, m = idx >> 6;
            xT[k * XS + m] = x[((size_t)(m0 + m) * T_LEN + i) * 64 + k];
        }
        __syncthreads();

        gru_mm<64>(g_WihT, bihs, xT, gi, 768);
        gru_mm<256>(g_WhhT, bhhs, hT, gh, 768);
        __syncthreads();

        // gate pointwise: thread -> (m = tid&15, n = tid>>4 + 32j)
        {
            const int pm = tid & 15;
            const int pn0 = tid >> 4;
#pragma unroll
            for (int j = 0; j < 8; ++j) {
                int n = pn0 + j * 32;
                float ir = gi[n * 16 + pm];
                float iz = gi[(256 + n) * 16 + pm];
                float in_ = gi[(512 + n) * 16 + pm];
                float hr = gh[n * 16 + pm];
                float hz = gh[(256 + n) * 16 + pm];
                float hn = gh[(512 + n) * 16 + pm];
                float h = hT[n * XS + pm];
                float r = sigm(ir + hr);
                float z = sigm(iz + hz);
                float nn = tanhf(in_ + r * hn);
                float hnew = (1.0f - z) * nn + z * h;
                float mk = mask[(size_t)(m0 + pm) * T_LEN + i];
                float hobs = mk * hnew + (1.0f - mk) * h;
                hT[n * XS + pm] = hobs;
                out[((size_t)(m0 + pm) * T_LEN + i) * 256 + n] = hobs;
            }
        }
        __syncthreads();

        if (i == T_LEN - 1) break;

        float t0v = t[i], t1v = t[i + 1];
        float dt = (t1v - t0v) * 0.25f;
        float tt = t0v;
        for (int sub = 0; sub < 4; ++sub) {
            // stage 1: f(tt, hT)
            gemm16<0>(g_W1F, hT, a1, b1s, w1ls, tt, true, 0, 0, 0, 0, 0.f); __syncthreads();
            gemm16<0>(g_W2F, a1, a2, b2s, 0, 0.f, false, 0, 0, 0, 0, 0.f); __syncthreads();
            gemm16<1>(g_W3F, a2, 0, 0, 0, 0.f, false, hT, yT, ka, b3s, dt); __syncthreads();
            // stage 2: f(tt+dt/2, yT)
            gemm16<0>(g_W1F, yT, a1, b1s, w1ls, tt + 0.5f * dt, true, 0, 0, 0, 0, 0.f); __syncthreads();
            gemm16<0>(g_W2F, a1, a2, b2s, 0, 0.f, false, 0, 0, 0, 0, 0.f); __syncthreads();
            gemm16<2>(g_W3F, a2, 0, 0, 0, 0.f, false, hT, yT, ka, b3s, dt); __syncthreads();
            // stage 3: f(tt+dt/2, yT)
            gemm16<0>(g_W1F, yT, a1, b1s, w1ls, tt + 0.5f * dt, true, 0, 0, 0, 0, 0.f); __syncthreads();
            gemm16<0>(g_W2F, a1, a2, b2s, 0, 0.f, false, 0, 0, 0, 0, 0.f); __syncthreads();
            gemm16<3>(g_W3F, a2, 0, 0, 0, 0.f, false, hT, yT, ka, b3s, dt); __syncthreads();
            // stage 4: f(tt+dt, yT)
            gemm16<0>(g_W1F, yT, a1, b1s, w1ls, tt + dt, true, 0, 0, 0, 0, 0.f); __syncthreads();
            gemm16<0>(g_W2F, a1, a2, b2s, 0, 0.f, false, 0, 0, 0, 0, 0.f); __syncthreads();
            gemm16<4>(g_W3F, a2, 0, 0, 0, 0.f, false, hT, yT, ka, b3s, dt); __syncthreads();
            tt += dt;
        }
    }
}

extern "C" void kernel_launch(void* const* d_in, const int* in_sizes, int n_in,
                              void* d_out, int out_size) {
    const float* x    = (const float*)d_in[0];
    const float* t    = (const float*)d_in[1];
    const float* mask = (const float*)d_in[2];
    const float* W_ih = (const float*)d_in[3];
    const float* W_hh = (const float*)d_in[4];
    const float* b_ih = (const float*)d_in[5];
    const float* b_hh = (const float*)d_in[6];
    const float* W1   = (const float*)d_in[7];
    const float* b1   = (const float*)d_in[8];
    const float* W2   = (const float*)d_in[9];
    const float* b2   = (const float*)d_in[10];
    const float* W3   = (const float*)d_in[11];
    const float* b3   = (const float*)d_in[12];
    float* out = (float*)d_out;

    prep_kernel<<<256, 256>>>(W_ih, W_hh, W1, W2, W3);

    const int smem_bytes = 34816 * sizeof(float);  // 139264
    cudaFuncSetAttribute(odernn_kernel,
                         cudaFuncAttributeMaxDynamicSharedMemorySize, smem_bytes);
    odernn_kernel<<<NCTA, NT, smem_bytes>>>(x, t, mask, b_ih, b_hh,
                                            b1, b2, b3, out);
}